// round 8
// baseline (speedup 1.0000x reference)
#include <cuda_runtime.h>
#include <cuda_bf16.h>
#include <math.h>
#include <stdint.h>

// ---------------- problem constants ----------------
#define HDIM 1024
#define IDIM 4096
#define NEXP 8
#define NTOK 4096          // B*S
#define NSLOT 8192         // NTOK*TOPK
#define TM 128             // CTA M tile
#define TN 64              // CTA N tile
#define KC 32              // K elems per chunk
#define NCH1 (HDIM / KC)   // 32
#define NCH2 (IDIM / KC)   // 128
#define PAD_MAX 9216
#define TILE_MAX 72
#define STRD 40            // smem row stride in elems -> 80B rows

// ---------------- device scratch (static, no allocs; zero-init) ----------------
__device__ int   g_perm[PAD_MAX];
__device__ int   g_tile_expert[TILE_MAX];
__device__ int   g_tile_row0[TILE_MAX];
// pre-split operands (hi/lo bf16, 16B chunks)
__device__ uint4 g_xh[(size_t)NTOK * HDIM / 8],        g_xl[(size_t)NTOK * HDIM / 8];
__device__ uint4 g_gh[(size_t)NEXP * IDIM * HDIM / 8], g_gl[(size_t)NEXP * IDIM * HDIM / 8];
__device__ uint4 g_uh[(size_t)NEXP * IDIM * HDIM / 8], g_ul[(size_t)NEXP * IDIM * HDIM / 8];
__device__ uint4 g_dh[(size_t)NEXP * HDIM * IDIM / 8], g_dl[(size_t)NEXP * HDIM * IDIM / 8];
__device__ uint4 g_zero[HDIM / 8];   // zero row for padding gathers
// act stored pre-split as bf16 hi/lo, row-major [PAD_MAX][IDIM]
__device__ uint4 g_act_hi[(size_t)PAD_MAX * IDIM / 8];
__device__ uint4 g_act_lo[(size_t)PAD_MAX * IDIM / 8];
__device__ float g_y[(size_t)NSLOT * HDIM];

// ---------------- helpers ----------------
__device__ __forceinline__ uint32_t smem_to_u32(const void* p) {
    uint32_t a;
    asm("{ .reg .u64 t; cvta.to.shared.u64 t, %1; cvt.u32.u64 %0, t; }" : "=r"(a) : "l"(p));
    return a;
}
__device__ __forceinline__ void cpa16(uint32_t dst, const void* src) {
    asm volatile("cp.async.cg.shared.global [%0], [%1], 16;"
                 :: "r"(dst), "l"(__cvta_generic_to_global(src)) : "memory");
}
#define CP_COMMIT() asm volatile("cp.async.commit_group;" ::: "memory")
#define CP_WAIT1()  asm volatile("cp.async.wait_group 1;" ::: "memory")
#define CP_WAIT0()  asm volatile("cp.async.wait_group 0;" ::: "memory")

__device__ __forceinline__ void ldsm4(uint32_t* r, uint32_t addr) {
    asm volatile("ldmatrix.sync.aligned.m8n8.x4.shared.b16 {%0,%1,%2,%3}, [%4];"
                 : "=r"(r[0]), "=r"(r[1]), "=r"(r[2]), "=r"(r[3]) : "r"(addr));
}
__device__ __forceinline__ void mma16816(float* c, const uint32_t* a, uint32_t b0, uint32_t b1) {
    asm volatile(
        "mma.sync.aligned.m16n8k16.row.col.f32.bf16.bf16.f32 "
        "{%0,%1,%2,%3}, {%4,%5,%6,%7}, {%8,%9}, {%0,%1,%2,%3};"
        : "+f"(c[0]), "+f"(c[1]), "+f"(c[2]), "+f"(c[3])
        : "r"(a[0]), "r"(a[1]), "r"(a[2]), "r"(a[3]), "r"(b0), "r"(b1));
}
// ldmatrix x4 address for a 16x16 block at (row, k) in a [.][STRD] bf16 tile
__device__ __forceinline__ uint32_t lds_addr(uint32_t base, int row, int k, int lane) {
    int r = row + (lane & 15);
    int kk = k + ((lane >> 4) << 3);
    return base + (uint32_t)(r * (STRD * 2) + kk * 2);
}
__device__ __forceinline__ float silu_mul(float g, float u) {
    return g * u / (1.0f + expf(-g));
}
__device__ __forceinline__ void split8(float4 v0, float4 v1, void* ph, void* pl) {
    float f[8] = {v0.x, v0.y, v0.z, v0.w, v1.x, v1.y, v1.z, v1.w};
    union { __nv_bfloat16 b[8]; uint4 u; } H, L;
#pragma unroll
    for (int j = 0; j < 8; j++) {
        __nv_bfloat16 h = __float2bfloat16(f[j]);
        H.b[j] = h;
        L.b[j] = __float2bfloat16(f[j] - __bfloat162float(h));
    }
    *(uint4*)ph = H.u;
    *(uint4*)pl = L.u;
}

// ---------------- pre-split conversion ----------------
// NOTE: destinations selected IN DEVICE CODE — __device__ symbols must never
// be passed as host-side kernel arguments (that was the R5/R6 bug).
__global__ __launch_bounds__(256)
void split_sel_kernel(const float4* __restrict__ src, int which, int n8) {
    int i = blockIdx.x * blockDim.x + threadIdx.x;
    if (i >= n8) return;
    uint4 *hi, *lo;
    switch (which) {
        case 0:  hi = g_xh; lo = g_xl; break;
        case 1:  hi = g_gh; lo = g_gl; break;
        case 2:  hi = g_uh; lo = g_ul; break;
        default: hi = g_dh; lo = g_dl; break;
    }
    split8(src[2 * i], src[2 * i + 1], &hi[i], &lo[i]);
}

// ---------------- routing (output-order invariant) ----------------
__global__ void route_kernel(const int* __restrict__ ei) {
    __shared__ int cnt[NEXP];
    __shared__ int cur[NEXP];
    int tid = threadIdx.x;
    if (tid < NEXP) cnt[tid] = 0;
    __syncthreads();
    for (int s = tid; s < NSLOT; s += blockDim.x) atomicAdd(&cnt[ei[s]], 1);
    __syncthreads();
    if (tid == 0) {
        int base = 0, tile = 0;
        for (int e = 0; e < NEXP; e++) {
            cur[e] = base;
            int nt = (cnt[e] + TM - 1) / TM;
            for (int j = 0; j < nt; j++) { g_tile_expert[tile] = e; g_tile_row0[tile] = base + j * TM; tile++; }
            base += nt * TM;
        }
        for (; tile < TILE_MAX; tile++) g_tile_expert[tile] = -1;
    }
    __syncthreads();
    for (int r = tid; r < PAD_MAX; r += blockDim.x) g_perm[r] = -1;
    __syncthreads();
    for (int s = tid; s < NSLOT; s += blockDim.x) {
        int e = ei[s];
        int pos = atomicAdd(&cur[e], 1);
        g_perm[pos] = s;
    }
}

// ---------------- GEMM1: act = silu(x.gateT) * (x.upT) ----------------
// dyn smem per stage (40960B): XH 0 | XL 10240 | GH 20480 | GL 25600 | UH 30720 | UL 35840
#define ST1 40960
#define SM1_TOKS (2 * ST1)
#define SM1_TOTAL (SM1_TOKS + 512)

__global__ __launch_bounds__(256, 2)
void gemm1_mma() {
    int e = g_tile_expert[blockIdx.y];
    if (e < 0) return;
    int row0 = g_tile_row0[blockIdx.y];
    int i0 = blockIdx.x * TN;

    extern __shared__ char smem[];
    uint32_t sb = smem_to_u32(smem);
    int* toks = (int*)(smem + SM1_TOKS);

    int tid = threadIdx.x;
    int lane = tid & 31, wid = tid >> 5;
    int mw = (wid >> 2) * 64;
    int nw = (wid & 3) * 16;

    if (tid < TM) {
        int p = g_perm[row0 + tid];
        toks[tid] = (p >= 0) ? (p >> 1) : -1;
    }
    __syncthreads();

    size_t wrow = (size_t)e * IDIM + i0;

    auto stage = [&](int st, int ch) {
        uint32_t sbase = sb + st * ST1;
        int kco = ch * (KC / 8);
#pragma unroll
        for (int l = 0; l < 4; l++) {            // X: 1024 tasks
            int s = tid + l * 256;
            int row = s >> 3, part = s & 7, hl = part >> 2, kq = part & 3;
            int tok = toks[row];
            const uint4* src = (tok >= 0)
                ? ((hl ? g_xl : g_xh) + ((size_t)tok * (HDIM / 8) + kco + kq))
                : (g_zero + kq);
            cpa16(sbase + hl * 10240 + row * 80 + kq * 16, src);
        }
#pragma unroll
        for (int l = 0; l < 4; l++) {            // G+U: 1024 tasks
            int t = tid + l * 256;
            int ten = t >> 9, r = (t >> 3) & 63, part = t & 7, hl = part >> 2, kq = part & 3;
            const uint4* src = (ten ? (hl ? g_ul : g_uh) : (hl ? g_gl : g_gh))
                + (wrow + r) * (HDIM / 8) + kco + kq;
            cpa16(sbase + 20480 + ten * 10240 + hl * 5120 + r * 80 + kq * 16, src);
        }
    };

    float cg[4][2][4], cu[4][2][4];
#pragma unroll
    for (int mf = 0; mf < 4; mf++)
#pragma unroll
        for (int nf = 0; nf < 2; nf++)
#pragma unroll
            for (int q = 0; q < 4; q++) { cg[mf][nf][q] = 0.f; cu[mf][nf][q] = 0.f; }

    stage(0, 0);
    CP_COMMIT();

    for (int ch = 0; ch < NCH1; ch++) {
        if (ch + 1 < NCH1) { stage((ch + 1) & 1, ch + 1); CP_COMMIT(); CP_WAIT1(); }
        else CP_WAIT0();
        __syncthreads();

        uint32_t bb = sb + (ch & 1) * ST1;
        uint32_t bXH = bb, bXL = bb + 10240;
        uint32_t bGH = bb + 20480, bGL = bb + 25600;
        uint32_t bUH = bb + 30720, bUL = bb + 35840;
#pragma unroll
        for (int ks = 0; ks < 2; ks++) {
            int kb = ks * 16;
            uint32_t bgh[4], bgl[4], buh[4], bul[4];
            ldsm4(bgh, lds_addr(bGH, nw, kb, lane));
            ldsm4(bgl, lds_addr(bGL, nw, kb, lane));
            ldsm4(buh, lds_addr(bUH, nw, kb, lane));
            ldsm4(bul, lds_addr(bUL, nw, kb, lane));
#pragma unroll
            for (int mf = 0; mf < 4; mf++) {
                uint32_t ah[4], al[4];
                ldsm4(ah, lds_addr(bXH, mw + mf * 16, kb, lane));
                ldsm4(al, lds_addr(bXL, mw + mf * 16, kb, lane));
#pragma unroll
                for (int nf = 0; nf < 2; nf++) {
                    mma16816(cg[mf][nf], ah, bgh[nf], bgh[nf + 2]);
                    mma16816(cg[mf][nf], ah, bgl[nf], bgl[nf + 2]);
                    mma16816(cg[mf][nf], al, bgh[nf], bgh[nf + 2]);
                    mma16816(cu[mf][nf], ah, buh[nf], buh[nf + 2]);
                    mma16816(cu[mf][nf], ah, bul[nf], bul[nf + 2]);
                    mma16816(cu[mf][nf], al, buh[nf], buh[nf + 2]);
                }
            }
        }
        __syncthreads();
    }

    // epilogue: silu*mul, split, store hi/lo bf16 act
    __nv_bfloat16* AH = (__nv_bfloat16*)g_act_hi;
    __nv_bfloat16* AL = (__nv_bfloat16*)g_act_lo;
#pragma unroll
    for (int mf = 0; mf < 4; mf++) {
#pragma unroll
        for (int nf = 0; nf < 2; nf++) {
            int mg = row0 + mw + mf * 16 + (lane >> 2);
            int ng = i0 + nw + nf * 8 + ((lane & 3) << 1);
#pragma unroll
            for (int h = 0; h < 2; h++) {
                float a0 = silu_mul(cg[mf][nf][h * 2],     cu[mf][nf][h * 2]);
                float a1 = silu_mul(cg[mf][nf][h * 2 + 1], cu[mf][nf][h * 2 + 1]);
                __nv_bfloat16 h0 = __float2bfloat16(a0), h1 = __float2bfloat16(a1);
                __nv_bfloat16 l0 = __float2bfloat16(a0 - __bfloat162float(h0));
                __nv_bfloat16 l1 = __float2bfloat16(a1 - __bfloat162float(h1));
                size_t idx = (size_t)(mg + h * 8) * IDIM + ng;
                *(__nv_bfloat162*)(AH + idx) = __halves2bfloat162(h0, h1);
                *(__nv_bfloat162*)(AL + idx) = __halves2bfloat162(l0, l1);
            }
        }
    }
}

// ---------------- GEMM2: y = ew * (act . downT) ----------------
// dyn smem per stage (30720B): AH 0 | AL 10240 | WH 20480 | WL 25600
#define ST2 30720
#define SM2_SLOT (2 * ST2)
#define SM2_SWT  (SM2_SLOT + 512)
#define SM2_TOTAL (SM2_SWT + 512)

__global__ __launch_bounds__(256, 2)
void gemm2_mma(const float* __restrict__ ew) {
    int e = g_tile_expert[blockIdx.y];
    if (e < 0) return;
    int row0 = g_tile_row0[blockIdx.y];
    int hb = blockIdx.x * TN;

    extern __shared__ char smem[];
    uint32_t sb = smem_to_u32(smem);
    int*   slots = (int*)(smem + SM2_SLOT);
    float* swt   = (float*)(smem + SM2_SWT);

    int tid = threadIdx.x;
    int lane = tid & 31, wid = tid >> 5;
    int mw = (wid >> 2) * 64;
    int nw = (wid & 3) * 16;

    if (tid < TM) {
        int p = g_perm[row0 + tid];
        slots[tid] = p;
        swt[tid] = (p >= 0) ? ew[p] : 0.f;
    }
    __syncthreads();

    size_t wrow = (size_t)e * HDIM + hb;

    auto stage = [&](int st, int ch) {
        uint32_t sbase = sb + st * ST2;
        int kco = ch * (KC / 8);
#pragma unroll
        for (int l = 0; l < 4; l++) {            // act: 1024 tasks
            int s = tid + l * 256;
            int row = s >> 3, part = s & 7, hl = part >> 2, kq = part & 3;
            const uint4* src = (hl ? g_act_lo : g_act_hi)
                + ((size_t)(row0 + row) * (IDIM / 8) + kco + kq);
            cpa16(sbase + hl * 10240 + row * 80 + kq * 16, src);
        }
#pragma unroll
        for (int l = 0; l < 2; l++) {            // down: 512 tasks
            int t = tid + l * 256;
            int r = t >> 3, part = t & 7, hl = part >> 2, kq = part & 3;
            const uint4* src = (hl ? g_dl : g_dh) + (wrow + r) * (IDIM / 8) + kco + kq;
            cpa16(sbase + 20480 + hl * 5120 + r * 80 + kq * 16, src);
        }
    };

    float acc[4][2][4];
#pragma unroll
    for (int mf = 0; mf < 4; mf++)
#pragma unroll
        for (int nf = 0; nf < 2; nf++)
#pragma unroll
            for (int q = 0; q < 4; q++) acc[mf][nf][q] = 0.f;

    stage(0, 0);
    CP_COMMIT();

    for (int ch = 0; ch < NCH2; ch++) {
        if (ch + 1 < NCH2) { stage((ch + 1) & 1, ch + 1); CP_COMMIT(); CP_WAIT1(); }
        else CP_WAIT0();
        __syncthreads();

        uint32_t bb = sb + (ch & 1) * ST2;
        uint32_t bAH = bb, bAL = bb + 10240;
        uint32_t bWH = bb + 20480, bWL = bb + 25600;
#pragma unroll
        for (int ks = 0; ks < 2; ks++) {
            int kb = ks * 16;
            uint32_t bwh[4], bwl[4];
            ldsm4(bwh, lds_addr(bWH, nw, kb, lane));
            ldsm4(bwl, lds_addr(bWL, nw, kb, lane));
#pragma unroll
            for (int mf = 0; mf < 4; mf++) {
                uint32_t ah[4], al[4];
                ldsm4(ah, lds_addr(bAH, mw + mf * 16, kb, lane));
                ldsm4(al, lds_addr(bAL, mw + mf * 16, kb, lane));
#pragma unroll
                for (int nf = 0; nf < 2; nf++) {
                    mma16816(acc[mf][nf], ah, bwh[nf], bwh[nf + 2]);
                    mma16816(acc[mf][nf], ah, bwl[nf], bwl[nf + 2]);
                    mma16816(acc[mf][nf], al, bwh[nf], bwh[nf + 2]);
                }
            }
        }
        __syncthreads();
    }

    // epilogue: scale by routing weight, scatter to per-slot y
#pragma unroll
    for (int mf = 0; mf < 4; mf++) {
#pragma unroll
        for (int nf = 0; nf < 2; nf++) {
            int ml = mw + mf * 16 + (lane >> 2);
            int ng = hb + nw + nf * 8 + ((lane & 3) << 1);
#pragma unroll
            for (int h = 0; h < 2; h++) {
                int m = ml + h * 8;
                int p = slots[m];
                if (p >= 0) {
                    float w = swt[m];
                    float2 o;
                    o.x = acc[mf][nf][h * 2] * w;
                    o.y = acc[mf][nf][h * 2 + 1] * w;
                    *(float2*)(g_y + (size_t)p * HDIM + ng) = o;
                }
            }
        }
    }
}

// ---------------- combine ----------------
__global__ void combine_kernel(float* __restrict__ out) {
    const int HQ = HDIM / 4;
    int i = blockIdx.x * blockDim.x + threadIdx.x;
    if (i >= NTOK * HQ) return;
    int t = i / HQ, hq = i - t * HQ;
    const float4* y4 = (const float4*)g_y;
    float4 a = y4[(size_t)(2 * t) * HQ + hq];
    float4 b = y4[(size_t)(2 * t + 1) * HQ + hq];
    float4 o;
    o.x = a.x + b.x; o.y = a.y + b.y; o.z = a.z + b.z; o.w = a.w + b.w;
    ((float4*)out)[(size_t)t * HQ + hq] = o;
}

extern "C" void kernel_launch(void* const* d_in, const int* in_sizes, int n_in,
                              void* d_out, int out_size) {
    const float* x    = (const float*)d_in[0];
    const int*   ei   = (const int*)d_in[1];
    const float* ew   = (const float*)d_in[2];
    const float* gate = (const float*)d_in[3];
    const float* up   = (const float*)d_in[4];
    const float* down = (const float*)d_in[5];
    float* out = (float*)d_out;

    static int attr_done = 0;
    if (!attr_done) {
        cudaFuncSetAttribute(gemm1_mma, cudaFuncAttributeMaxDynamicSharedMemorySize, SM1_TOTAL);
        cudaFuncSetAttribute(gemm2_mma, cudaFuncAttributeMaxDynamicSharedMemorySize, SM2_TOTAL);
        attr_done = 1;
    }

    const int WN8 = (int)((size_t)NEXP * IDIM * HDIM / 8);   // 4194304
    const int XN8 = (int)((size_t)NTOK * HDIM / 8);          // 524288

    route_kernel<<<1, 256>>>(ei);
    split_sel_kernel<<<(XN8 + 255) / 256, 256>>>((const float4*)x,    0, XN8);
    split_sel_kernel<<<(WN8 + 255) / 256, 256>>>((const float4*)gate, 1, WN8);
    split_sel_kernel<<<(WN8 + 255) / 256, 256>>>((const float4*)up,   2, WN8);
    split_sel_kernel<<<(WN8 + 255) / 256, 256>>>((const float4*)down, 3, WN8);

    gemm1_mma<<<dim3(IDIM / TN, TILE_MAX), 256, SM1_TOTAL>>>();
    gemm2_mma<<<dim3(HDIM / TN, TILE_MAX), 256, SM2_TOTAL>>>(ew);
    combine_kernel<<<(NTOK * (HDIM / 4) + 255) / 256, 256>>>(out);
}

// round 9
// speedup vs baseline: 1.5276x; 1.5276x over previous
#include <cuda_runtime.h>
#include <cuda_bf16.h>
#include <math.h>
#include <stdint.h>

// ---------------- problem constants ----------------
#define HDIM 1024
#define IDIM 4096
#define NEXP 8
#define NTOK 4096          // B*S
#define NSLOT 8192         // NTOK*TOPK
#define TM 128             // CTA M tile
#define TN 64              // CTA N tile
#define KC 32              // K elems per chunk
#define NCH1 (HDIM / KC)   // 32
#define NCH2 (IDIM / KC)   // 128
#define PAD_MAX 9216
#define TILE_MAX 72
#define STRD 40            // smem row stride in elems (32 + 8 pad) -> 80B rows

// ---------------- device scratch (static, no allocs; zero-init) ----------------
__device__ int   g_perm[PAD_MAX];
__device__ int   g_tile_expert[TILE_MAX];
__device__ int   g_tile_row0[TILE_MAX];
// pre-split weights (hi/lo bf16, 16B chunks)
__device__ uint4 g_gh[(size_t)NEXP * IDIM * HDIM / 8], g_gl[(size_t)NEXP * IDIM * HDIM / 8];
__device__ uint4 g_uh[(size_t)NEXP * IDIM * HDIM / 8], g_ul[(size_t)NEXP * IDIM * HDIM / 8];
__device__ uint4 g_dh[(size_t)NEXP * HDIM * IDIM / 8], g_dl[(size_t)NEXP * HDIM * IDIM / 8];
// act stored pre-split as bf16 hi/lo, row-major [PAD_MAX][IDIM]
__device__ uint4 g_act_hi[(size_t)PAD_MAX * IDIM / 8];
__device__ uint4 g_act_lo[(size_t)PAD_MAX * IDIM / 8];
__device__ float g_y[(size_t)NSLOT * HDIM];

// ---------------- helpers ----------------
__device__ __forceinline__ uint32_t smem_to_u32(const void* p) {
    uint32_t a;
    asm("{ .reg .u64 t; cvta.to.shared.u64 t, %1; cvt.u32.u64 %0, t; }" : "=r"(a) : "l"(p));
    return a;
}
__device__ __forceinline__ void ldsm4(uint32_t* r, uint32_t addr) {
    asm volatile("ldmatrix.sync.aligned.m8n8.x4.shared.b16 {%0,%1,%2,%3}, [%4];"
                 : "=r"(r[0]), "=r"(r[1]), "=r"(r[2]), "=r"(r[3]) : "r"(addr));
}
__device__ __forceinline__ void mma16816(float* c, const uint32_t* a, uint32_t b0, uint32_t b1) {
    asm volatile(
        "mma.sync.aligned.m16n8k16.row.col.f32.bf16.bf16.f32 "
        "{%0,%1,%2,%3}, {%4,%5,%6,%7}, {%8,%9}, {%0,%1,%2,%3};"
        : "+f"(c[0]), "+f"(c[1]), "+f"(c[2]), "+f"(c[3])
        : "r"(a[0]), "r"(a[1]), "r"(a[2]), "r"(a[3]), "r"(b0), "r"(b1));
}
// ldmatrix x4 address for a 16x16 block at (row, k) in a [.][STRD] bf16 tile
__device__ __forceinline__ uint32_t lds_addr(uint32_t base, int row, int k, int lane) {
    int r = row + (lane & 15);
    int kk = k + ((lane >> 4) << 3);
    return base + (uint32_t)(r * (STRD * 2) + kk * 2);
}
__device__ __forceinline__ float silu_mul(float g, float u) {
    return g * u / (1.0f + expf(-g));
}
__device__ __forceinline__ void split8(float4 v0, float4 v1, void* ph, void* pl) {
    float f[8] = {v0.x, v0.y, v0.z, v0.w, v1.x, v1.y, v1.z, v1.w};
    union { __nv_bfloat16 b[8]; uint4 u; } H, L;
#pragma unroll
    for (int j = 0; j < 8; j++) {
        __nv_bfloat16 h = __float2bfloat16(f[j]);
        H.b[j] = h;
        L.b[j] = __float2bfloat16(f[j] - __bfloat162float(h));
    }
    *(uint4*)ph = H.u;
    *(uint4*)pl = L.u;
}

// ---------------- pre-split conversion (destinations chosen in device code!) ----------------
__global__ __launch_bounds__(256)
void split_sel_kernel(const float4* __restrict__ src, int which, int n8) {
    int i = blockIdx.x * blockDim.x + threadIdx.x;
    if (i >= n8) return;
    uint4 *hi, *lo;
    switch (which) {
        case 1:  hi = g_gh; lo = g_gl; break;
        case 2:  hi = g_uh; lo = g_ul; break;
        default: hi = g_dh; lo = g_dl; break;
    }
    split8(src[2 * i], src[2 * i + 1], &hi[i], &lo[i]);
}

// ---------------- routing (output-order invariant) ----------------
__global__ void route_kernel(const int* __restrict__ ei) {
    __shared__ int cnt[NEXP];
    __shared__ int cur[NEXP];
    int tid = threadIdx.x;
    if (tid < NEXP) cnt[tid] = 0;
    __syncthreads();
    for (int s = tid; s < NSLOT; s += blockDim.x) atomicAdd(&cnt[ei[s]], 1);
    __syncthreads();
    if (tid == 0) {
        int base = 0, tile = 0;
        for (int e = 0; e < NEXP; e++) {
            cur[e] = base;
            int nt = (cnt[e] + TM - 1) / TM;
            for (int j = 0; j < nt; j++) { g_tile_expert[tile] = e; g_tile_row0[tile] = base + j * TM; tile++; }
            base += nt * TM;
        }
        for (; tile < TILE_MAX; tile++) g_tile_expert[tile] = -1;
    }
    __syncthreads();
    for (int r = tid; r < PAD_MAX; r += blockDim.x) g_perm[r] = -1;
    __syncthreads();
    for (int s = tid; s < NSLOT; s += blockDim.x) {
        int e = ei[s];
        int pos = atomicAdd(&cur[e], 1);
        g_perm[pos] = s;
    }
}

// ---------------- GEMM1: act = silu(x.gateT) * (x.upT) ----------------
__global__ __launch_bounds__(256, 2)
void gemm1_mma(const float* __restrict__ x) {
    int e = g_tile_expert[blockIdx.y];
    if (e < 0) return;
    int row0 = g_tile_row0[blockIdx.y];
    int i0 = blockIdx.x * TN;

    __shared__ __align__(16) __nv_bfloat16 sXH[TM * STRD], sXL[TM * STRD];
    __shared__ __align__(16) __nv_bfloat16 sGH[TN * STRD], sGL[TN * STRD];
    __shared__ __align__(16) __nv_bfloat16 sUH[TN * STRD], sUL[TN * STRD];
    __shared__ int toks[TM];

    int tid = threadIdx.x;
    int lane = tid & 31, wid = tid >> 5;
    int mw = (wid >> 2) * 64;      // warp M offset (0 or 64)
    int nw = (wid & 3) * 16;       // warp N offset

    if (tid < TM) {
        int p = g_perm[row0 + tid];
        toks[tid] = (p >= 0) ? (p >> 1) : -1;
    }
    __syncthreads();

    uint32_t bXH = smem_to_u32(sXH), bXL = smem_to_u32(sXL);
    uint32_t bGH = smem_to_u32(sGH), bGL = smem_to_u32(sGL);
    uint32_t bUH = smem_to_u32(sUH), bUL = smem_to_u32(sUL);
    size_t wrow = (size_t)e * IDIM + i0;

    float cg[4][2][4], cu[4][2][4];
#pragma unroll
    for (int mf = 0; mf < 4; mf++)
#pragma unroll
        for (int nf = 0; nf < 2; nf++)
#pragma unroll
            for (int q = 0; q < 4; q++) { cg[mf][nf][q] = 0.f; cu[mf][nf][q] = 0.f; }

    for (int ch = 0; ch < NCH1; ch++) {
        int h0 = ch * KC;
        int kco = ch * (KC / 8);
        // stage x (gathered rows, in-kernel split): 512 tasks of 8 elems
#pragma unroll
        for (int l = 0; l < 2; l++) {
            int s = tid + l * 256;
            int row = s >> 2, k0 = (s & 3) << 3;
            int tok = toks[row];
            float4 v0 = make_float4(0.f, 0.f, 0.f, 0.f), v1 = v0;
            if (tok >= 0) {
                const float4* p = (const float4*)(x + (size_t)tok * HDIM + h0 + k0);
                v0 = p[0]; v1 = p[1];
            }
            int off = row * STRD + k0;
            split8(v0, v1, sXH + off, sXL + off);
        }
        // stage gate + up from pre-split arrays: pure uint4 copies
        {
            int row = tid >> 2, kq = tid & 3, k0 = kq << 3;
            int off = row * STRD + k0;
            size_t gidx = (wrow + row) * (HDIM / 8) + kco + kq;
            *(uint4*)(sGH + off) = g_gh[gidx];
            *(uint4*)(sGL + off) = g_gl[gidx];
            *(uint4*)(sUH + off) = g_uh[gidx];
            *(uint4*)(sUL + off) = g_ul[gidx];
        }
        __syncthreads();

#pragma unroll
        for (int ks = 0; ks < 2; ks++) {
            int kb = ks * 16;
            uint32_t bgh[4], bgl[4], buh[4], bul[4];
            ldsm4(bgh, lds_addr(bGH, nw, kb, lane));
            ldsm4(bgl, lds_addr(bGL, nw, kb, lane));
            ldsm4(buh, lds_addr(bUH, nw, kb, lane));
            ldsm4(bul, lds_addr(bUL, nw, kb, lane));
#pragma unroll
            for (int mf = 0; mf < 4; mf++) {
                uint32_t ah[4], al[4];
                ldsm4(ah, lds_addr(bXH, mw + mf * 16, kb, lane));
                ldsm4(al, lds_addr(bXL, mw + mf * 16, kb, lane));
#pragma unroll
                for (int nf = 0; nf < 2; nf++) {
                    mma16816(cg[mf][nf], ah, bgh[nf], bgh[nf + 2]);
                    mma16816(cg[mf][nf], ah, bgl[nf], bgl[nf + 2]);
                    mma16816(cg[mf][nf], al, bgh[nf], bgh[nf + 2]);
                    mma16816(cu[mf][nf], ah, buh[nf], buh[nf + 2]);
                    mma16816(cu[mf][nf], ah, bul[nf], bul[nf + 2]);
                    mma16816(cu[mf][nf], al, buh[nf], buh[nf + 2]);
                }
            }
        }
        __syncthreads();
    }

    // epilogue: silu*mul, split, store hi/lo bf16 act
    __nv_bfloat16* AH = (__nv_bfloat16*)g_act_hi;
    __nv_bfloat16* AL = (__nv_bfloat16*)g_act_lo;
#pragma unroll
    for (int mf = 0; mf < 4; mf++) {
#pragma unroll
        for (int nf = 0; nf < 2; nf++) {
            int mg = row0 + mw + mf * 16 + (lane >> 2);
            int ng = i0 + nw + nf * 8 + ((lane & 3) << 1);
#pragma unroll
            for (int h = 0; h < 2; h++) {
                float a0 = silu_mul(cg[mf][nf][h * 2],     cu[mf][nf][h * 2]);
                float a1 = silu_mul(cg[mf][nf][h * 2 + 1], cu[mf][nf][h * 2 + 1]);
                __nv_bfloat16 h0 = __float2bfloat16(a0), h1 = __float2bfloat16(a1);
                __nv_bfloat16 l0 = __float2bfloat16(a0 - __bfloat162float(h0));
                __nv_bfloat16 l1 = __float2bfloat16(a1 - __bfloat162float(h1));
                size_t idx = (size_t)(mg + h * 8) * IDIM + ng;
                *(__nv_bfloat162*)(AH + idx) = __halves2bfloat162(h0, h1);
                *(__nv_bfloat162*)(AL + idx) = __halves2bfloat162(l0, l1);
            }
        }
    }
}

// ---------------- GEMM2: y = ew * (act . downT) ----------------
__global__ __launch_bounds__(256, 2)
void gemm2_mma(const float* __restrict__ ew) {
    int e = g_tile_expert[blockIdx.y];
    if (e < 0) return;
    int row0 = g_tile_row0[blockIdx.y];
    int hb = blockIdx.x * TN;

    __shared__ __align__(16) __nv_bfloat16 sAH[TM * STRD], sAL[TM * STRD];
    __shared__ __align__(16) __nv_bfloat16 sWH[TN * STRD], sWL[TN * STRD];
    __shared__ int   slots[TM];
    __shared__ float swt[TM];

    int tid = threadIdx.x;
    int lane = tid & 31, wid = tid >> 5;
    int mw = (wid >> 2) * 64;
    int nw = (wid & 3) * 16;

    if (tid < TM) {
        int p = g_perm[row0 + tid];
        slots[tid] = p;
        swt[tid] = (p >= 0) ? ew[p] : 0.f;
    }
    __syncthreads();

    uint32_t bAH = smem_to_u32(sAH), bAL = smem_to_u32(sAL);
    uint32_t bWH = smem_to_u32(sWH), bWL = smem_to_u32(sWL);
    size_t wrow = (size_t)e * HDIM + hb;

    float acc[4][2][4];
#pragma unroll
    for (int mf = 0; mf < 4; mf++)
#pragma unroll
        for (int nf = 0; nf < 2; nf++)
#pragma unroll
            for (int q = 0; q < 4; q++) acc[mf][nf][q] = 0.f;

    const uint4* ahp = g_act_hi;
    const uint4* alp = g_act_lo;

    for (int ch = 0; ch < NCH2; ch++) {
        int kco = ch * (KC / 8);
        // stage act (pure 16B copies, already split bf16)
#pragma unroll
        for (int l = 0; l < 2; l++) {
            int s = tid + l * 256;
            int row = s >> 2, kq = s & 3, k0 = kq << 3;
            size_t gx = (size_t)(row0 + row) * (IDIM / 8) + kco + kq;
            int off = row * STRD + k0;
            *(uint4*)(sAH + off) = ahp[gx];
            *(uint4*)(sAL + off) = alp[gx];
        }
        // stage down from pre-split arrays: pure uint4 copies
        {
            int row = tid >> 2, kq = tid & 3, k0 = kq << 3;
            int off = row * STRD + k0;
            size_t gidx = (wrow + row) * (IDIM / 8) + kco + kq;
            *(uint4*)(sWH + off) = g_dh[gidx];
            *(uint4*)(sWL + off) = g_dl[gidx];
        }
        __syncthreads();

#pragma unroll
        for (int ks = 0; ks < 2; ks++) {
            int kb = ks * 16;
            uint32_t bwh[4], bwl[4];
            ldsm4(bwh, lds_addr(bWH, nw, kb, lane));
            ldsm4(bwl, lds_addr(bWL, nw, kb, lane));
#pragma unroll
            for (int mf = 0; mf < 4; mf++) {
                uint32_t ah[4], al[4];
                ldsm4(ah, lds_addr(bAH, mw + mf * 16, kb, lane));
                ldsm4(al, lds_addr(bAL, mw + mf * 16, kb, lane));
#pragma unroll
                for (int nf = 0; nf < 2; nf++) {
                    mma16816(acc[mf][nf], ah, bwh[nf], bwh[nf + 2]);
                    mma16816(acc[mf][nf], ah, bwl[nf], bwl[nf + 2]);
                    mma16816(acc[mf][nf], al, bwh[nf], bwh[nf + 2]);
                }
            }
        }
        __syncthreads();
    }

    // epilogue: scale by routing weight, scatter to per-slot y
#pragma unroll
    for (int mf = 0; mf < 4; mf++) {
#pragma unroll
        for (int nf = 0; nf < 2; nf++) {
            int ml = mw + mf * 16 + (lane >> 2);
            int ng = hb + nw + nf * 8 + ((lane & 3) << 1);
#pragma unroll
            for (int h = 0; h < 2; h++) {
                int m = ml + h * 8;
                int p = slots[m];
                if (p >= 0) {
                    float w = swt[m];
                    float2 o;
                    o.x = acc[mf][nf][h * 2] * w;
                    o.y = acc[mf][nf][h * 2 + 1] * w;
                    *(float2*)(g_y + (size_t)p * HDIM + ng) = o;
                }
            }
        }
    }
}

// ---------------- combine ----------------
__global__ void combine_kernel(float* __restrict__ out) {
    const int HQ = HDIM / 4;
    int i = blockIdx.x * blockDim.x + threadIdx.x;
    if (i >= NTOK * HQ) return;
    int t = i / HQ, hq = i - t * HQ;
    const float4* y4 = (const float4*)g_y;
    float4 a = y4[(size_t)(2 * t) * HQ + hq];
    float4 b = y4[(size_t)(2 * t + 1) * HQ + hq];
    float4 o;
    o.x = a.x + b.x; o.y = a.y + b.y; o.z = a.z + b.z; o.w = a.w + b.w;
    ((float4*)out)[(size_t)t * HQ + hq] = o;
}

extern "C" void kernel_launch(void* const* d_in, const int* in_sizes, int n_in,
                              void* d_out, int out_size) {
    const float* x    = (const float*)d_in[0];
    const int*   ei   = (const int*)d_in[1];
    const float* ew   = (const float*)d_in[2];
    const float* gate = (const float*)d_in[3];
    const float* up   = (const float*)d_in[4];
    const float* down = (const float*)d_in[5];
    float* out = (float*)d_out;

    const int WN8 = (int)((size_t)NEXP * IDIM * HDIM / 8);   // 4194304

    route_kernel<<<1, 256>>>(ei);
    split_sel_kernel<<<(WN8 + 255) / 256, 256>>>((const float4*)gate, 1, WN8);
    split_sel_kernel<<<(WN8 + 255) / 256, 256>>>((const float4*)up,   2, WN8);
    split_sel_kernel<<<(WN8 + 255) / 256, 256>>>((const float4*)down, 3, WN8);

    gemm1_mma<<<dim3(IDIM / TN, TILE_MAX), 256>>>(x);
    gemm2_mma<<<dim3(HDIM / TN, TILE_MAX), 256>>>(ew);
    combine_kernel<<<(NTOK * (HDIM / 4) + 255) / 256, 256>>>(out);
}

// round 10
// speedup vs baseline: 1.6438x; 1.0761x over previous
#include <cuda_runtime.h>
#include <cuda_bf16.h>
#include <math.h>
#include <stdint.h>

// ---------------- problem constants ----------------
#define HDIM 1024
#define IDIM 4096
#define NEXP 8
#define NTOK 4096          // B*S
#define NSLOT 8192         // NTOK*TOPK
#define TM 128             // CTA M tile
#define TN 64              // CTA N tile
#define KC 32              // K elems per chunk
#define NCH1 (HDIM / KC)   // 32
#define NCH2 (IDIM / KC)   // 128
#define PAD_MAX 9216
#define TILE_MAX 72
#define STRD 40            // smem row stride in elems (32 + 8 pad) -> 80B rows

// ---------------- device scratch (static, no allocs) ----------------
__device__ int   g_perm[PAD_MAX];
__device__ int   g_tile_expert[TILE_MAX];
__device__ int   g_tile_row0[TILE_MAX];
// act stored pre-split as bf16 hi/lo, row-major [PAD_MAX][IDIM]
__device__ uint4 g_act_hi[(size_t)PAD_MAX * IDIM / 8];
__device__ uint4 g_act_lo[(size_t)PAD_MAX * IDIM / 8];
__device__ float g_y[(size_t)NSLOT * HDIM];

// ---------------- helpers ----------------
__device__ __forceinline__ uint32_t smem_to_u32(const void* p) {
    uint32_t a;
    asm("{ .reg .u64 t; cvta.to.shared.u64 t, %1; cvt.u32.u64 %0, t; }" : "=r"(a) : "l"(p));
    return a;
}
__device__ __forceinline__ void ldsm4(uint32_t* r, uint32_t addr) {
    asm volatile("ldmatrix.sync.aligned.m8n8.x4.shared.b16 {%0,%1,%2,%3}, [%4];"
                 : "=r"(r[0]), "=r"(r[1]), "=r"(r[2]), "=r"(r[3]) : "r"(addr));
}
__device__ __forceinline__ void mma16816(float* c, const uint32_t* a, uint32_t b0, uint32_t b1) {
    asm volatile(
        "mma.sync.aligned.m16n8k16.row.col.f32.bf16.bf16.f32 "
        "{%0,%1,%2,%3}, {%4,%5,%6,%7}, {%8,%9}, {%0,%1,%2,%3};"
        : "+f"(c[0]), "+f"(c[1]), "+f"(c[2]), "+f"(c[3])
        : "r"(a[0]), "r"(a[1]), "r"(a[2]), "r"(a[3]), "r"(b0), "r"(b1));
}
// ldmatrix x4 address for a 16x16 block at (row, k) in a [.][STRD] bf16 tile
__device__ __forceinline__ uint32_t lds_addr(uint32_t base, int row, int k, int lane) {
    int r = row + (lane & 15);
    int kk = k + ((lane >> 4) << 3);
    return base + (uint32_t)(r * (STRD * 2) + kk * 2);
}
__device__ __forceinline__ float silu_mul(float g, float u) {
    return g * u / (1.0f + expf(-g));
}
__device__ __forceinline__ void split8(float4 v0, float4 v1, void* ph, void* pl) {
    float f[8] = {v0.x, v0.y, v0.z, v0.w, v1.x, v1.y, v1.z, v1.w};
    union { __nv_bfloat16 b[8]; uint4 u; } H, L;
#pragma unroll
    for (int j = 0; j < 8; j++) {
        __nv_bfloat16 h = __float2bfloat16(f[j]);
        H.b[j] = h;
        L.b[j] = __float2bfloat16(f[j] - __bfloat162float(h));
    }
    *(uint4*)ph = H.u;
    *(uint4*)pl = L.u;
}

// ---------------- routing (output-order invariant) ----------------
__global__ void route_kernel(const int* __restrict__ ei) {
    __shared__ int cnt[NEXP];
    __shared__ int cur[NEXP];
    int tid = threadIdx.x;
    if (tid < NEXP) cnt[tid] = 0;
    __syncthreads();
    for (int s = tid; s < NSLOT; s += blockDim.x) atomicAdd(&cnt[ei[s]], 1);
    __syncthreads();
    if (tid == 0) {
        int base = 0, tile = 0;
        for (int e = 0; e < NEXP; e++) {
            cur[e] = base;
            int nt = (cnt[e] + TM - 1) / TM;
            for (int j = 0; j < nt; j++) { g_tile_expert[tile] = e; g_tile_row0[tile] = base + j * TM; tile++; }
            base += nt * TM;
        }
        for (; tile < TILE_MAX; tile++) g_tile_expert[tile] = -1;
    }
    __syncthreads();
    for (int r = tid; r < PAD_MAX; r += blockDim.x) g_perm[r] = -1;
    __syncthreads();
    for (int s = tid; s < NSLOT; s += blockDim.x) {
        int e = ei[s];
        int pos = atomicAdd(&cur[e], 1);
        g_perm[pos] = s;
    }
}

// ---------------- GEMM1: act = silu(x.gateT) * (x.upT) ----------------
// Weight tiles are prefetched one chunk ahead into registers (LDG hidden
// behind the MMA section); x stays loop-top (mostly L2 hits, rows shared
// across all 64 i-tile CTAs).
__global__ __launch_bounds__(256, 2)
void gemm1_mma(const float* __restrict__ x,
               const float* __restrict__ gate,
               const float* __restrict__ up) {
    int e = g_tile_expert[blockIdx.y];
    if (e < 0) return;
    int row0 = g_tile_row0[blockIdx.y];
    int i0 = blockIdx.x * TN;

    __shared__ __align__(16) __nv_bfloat16 sXH[TM * STRD], sXL[TM * STRD];
    __shared__ __align__(16) __nv_bfloat16 sGH[TN * STRD], sGL[TN * STRD];
    __shared__ __align__(16) __nv_bfloat16 sUH[TN * STRD], sUL[TN * STRD];
    __shared__ int toks[TM];

    int tid = threadIdx.x;
    int lane = tid & 31, wid = tid >> 5;
    int mw = (wid >> 2) * 64;      // warp M offset (0 or 64)
    int nw = (wid & 3) * 16;       // warp N offset

    if (tid < TM) {
        int p = g_perm[row0 + tid];
        toks[tid] = (p >= 0) ? (p >> 1) : -1;
    }
    __syncthreads();

    uint32_t bXH = smem_to_u32(sXH), bXL = smem_to_u32(sXL);
    uint32_t bGH = smem_to_u32(sGH), bGL = smem_to_u32(sGL);
    uint32_t bUH = smem_to_u32(sUH), bUL = smem_to_u32(sUL);

    // weight-staging task for this thread (fixed across chunks)
    int wr = tid >> 2, wk0 = (tid & 3) << 3;
    const float* gptr = gate + ((size_t)e * IDIM + i0 + wr) * HDIM + wk0;
    const float* uptr = up   + ((size_t)e * IDIM + i0 + wr) * HDIM + wk0;
    int woff = wr * STRD + wk0;

    float cg[4][2][4], cu[4][2][4];
#pragma unroll
    for (int mf = 0; mf < 4; mf++)
#pragma unroll
        for (int nf = 0; nf < 2; nf++)
#pragma unroll
            for (int q = 0; q < 4; q++) { cg[mf][nf][q] = 0.f; cu[mf][nf][q] = 0.f; }

    // prologue: prefetch weights for chunk 0
    float4 pg0 = *(const float4*)(gptr);
    float4 pg1 = *(const float4*)(gptr + 4);
    float4 pu0 = *(const float4*)(uptr);
    float4 pu1 = *(const float4*)(uptr + 4);

    for (int ch = 0; ch < NCH1; ch++) {
        int h0 = ch * KC;
        // stage x (gathered rows): 512 tasks of 8 elems
#pragma unroll
        for (int l = 0; l < 2; l++) {
            int s = tid + l * 256;
            int row = s >> 2, k0 = (s & 3) << 3;
            int tok = toks[row];
            float4 v0 = make_float4(0.f, 0.f, 0.f, 0.f), v1 = v0;
            if (tok >= 0) {
                const float4* p = (const float4*)(x + (size_t)tok * HDIM + h0 + k0);
                v0 = p[0]; v1 = p[1];
            }
            int off = row * STRD + k0;
            split8(v0, v1, sXH + off, sXL + off);
        }
        // stage weights from prefetched registers
        split8(pg0, pg1, sGH + woff, sGL + woff);
        split8(pu0, pu1, sUH + woff, sUL + woff);
        __syncthreads();

        // prefetch next chunk's weights (latency hidden behind MMAs below)
        if (ch + 1 < NCH1) {
            int hn = (ch + 1) * KC;
            pg0 = *(const float4*)(gptr + hn);
            pg1 = *(const float4*)(gptr + hn + 4);
            pu0 = *(const float4*)(uptr + hn);
            pu1 = *(const float4*)(uptr + hn + 4);
        }

#pragma unroll
        for (int ks = 0; ks < 2; ks++) {
            int kb = ks * 16;
            uint32_t bgh[4], bgl[4], buh[4], bul[4];
            ldsm4(bgh, lds_addr(bGH, nw, kb, lane));
            ldsm4(bgl, lds_addr(bGL, nw, kb, lane));
            ldsm4(buh, lds_addr(bUH, nw, kb, lane));
            ldsm4(bul, lds_addr(bUL, nw, kb, lane));
#pragma unroll
            for (int mf = 0; mf < 4; mf++) {
                uint32_t ah[4], al[4];
                ldsm4(ah, lds_addr(bXH, mw + mf * 16, kb, lane));
                ldsm4(al, lds_addr(bXL, mw + mf * 16, kb, lane));
#pragma unroll
                for (int nf = 0; nf < 2; nf++) {
                    mma16816(cg[mf][nf], ah, bgh[nf], bgh[nf + 2]);
                    mma16816(cg[mf][nf], ah, bgl[nf], bgl[nf + 2]);
                    mma16816(cg[mf][nf], al, bgh[nf], bgh[nf + 2]);
                    mma16816(cu[mf][nf], ah, buh[nf], buh[nf + 2]);
                    mma16816(cu[mf][nf], ah, bul[nf], bul[nf + 2]);
                    mma16816(cu[mf][nf], al, buh[nf], buh[nf + 2]);
                }
            }
        }
        __syncthreads();
    }

    // epilogue: silu*mul, split, store hi/lo bf16 act
    __nv_bfloat16* AH = (__nv_bfloat16*)g_act_hi;
    __nv_bfloat16* AL = (__nv_bfloat16*)g_act_lo;
#pragma unroll
    for (int mf = 0; mf < 4; mf++) {
#pragma unroll
        for (int nf = 0; nf < 2; nf++) {
            int mg = row0 + mw + mf * 16 + (lane >> 2);
            int ng = i0 + nw + nf * 8 + ((lane & 3) << 1);
#pragma unroll
            for (int h = 0; h < 2; h++) {
                float a0 = silu_mul(cg[mf][nf][h * 2],     cu[mf][nf][h * 2]);
                float a1 = silu_mul(cg[mf][nf][h * 2 + 1], cu[mf][nf][h * 2 + 1]);
                __nv_bfloat16 h0 = __float2bfloat16(a0), h1 = __float2bfloat16(a1);
                __nv_bfloat16 l0 = __float2bfloat16(a0 - __bfloat162float(h0));
                __nv_bfloat16 l1 = __float2bfloat16(a1 - __bfloat162float(h1));
                size_t idx = (size_t)(mg + h * 8) * IDIM + ng;
                *(__nv_bfloat162*)(AH + idx) = __halves2bfloat162(h0, h1);
                *(__nv_bfloat162*)(AL + idx) = __halves2bfloat162(l0, l1);
            }
        }
    }
}

// ---------------- GEMM2: y = ew * (act . downT) ----------------
// Both operands register-prefetched one chunk ahead (acc only 32 regs here).
__global__ __launch_bounds__(256, 2)
void gemm2_mma(const float* __restrict__ down,
               const float* __restrict__ ew) {
    int e = g_tile_expert[blockIdx.y];
    if (e < 0) return;
    int row0 = g_tile_row0[blockIdx.y];
    int hb = blockIdx.x * TN;

    __shared__ __align__(16) __nv_bfloat16 sAH[TM * STRD], sAL[TM * STRD];
    __shared__ __align__(16) __nv_bfloat16 sWH[TN * STRD], sWL[TN * STRD];
    __shared__ int   slots[TM];
    __shared__ float swt[TM];

    int tid = threadIdx.x;
    int lane = tid & 31, wid = tid >> 5;
    int mw = (wid >> 2) * 64;
    int nw = (wid & 3) * 16;

    if (tid < TM) {
        int p = g_perm[row0 + tid];
        slots[tid] = p;
        swt[tid] = (p >= 0) ? ew[p] : 0.f;
    }
    __syncthreads();

    uint32_t bAH = smem_to_u32(sAH), bAL = smem_to_u32(sAL);
    uint32_t bWH = smem_to_u32(sWH), bWL = smem_to_u32(sWL);

    // fixed per-thread staging tasks
    // act: 2 tasks (rows tid>>2 and (tid+256)>>2)
    int ar0 = tid >> 2, ak0 = tid & 3;
    int ar1 = (tid + 256) >> 2, ak1 = ak0;
    const uint4* ahp0 = g_act_hi + (size_t)(row0 + ar0) * (IDIM / 8) + ak0;
    const uint4* alp0 = g_act_lo + (size_t)(row0 + ar0) * (IDIM / 8) + ak0;
    const uint4* ahp1 = g_act_hi + (size_t)(row0 + ar1) * (IDIM / 8) + ak1;
    const uint4* alp1 = g_act_lo + (size_t)(row0 + ar1) * (IDIM / 8) + ak1;
    int aoff0 = ar0 * STRD + (ak0 << 3);
    int aoff1 = ar1 * STRD + (ak1 << 3);
    // down: 1 task
    int wr = tid >> 2, wk0 = (tid & 3) << 3;
    const float* wptr = down + ((size_t)e * HDIM + hb + wr) * IDIM + wk0;
    int woff = wr * STRD + wk0;

    float acc[4][2][4];
#pragma unroll
    for (int mf = 0; mf < 4; mf++)
#pragma unroll
        for (int nf = 0; nf < 2; nf++)
#pragma unroll
            for (int q = 0; q < 4; q++) acc[mf][nf][q] = 0.f;

    // prologue: prefetch chunk 0
    uint4 pa0h = ahp0[0], pa0l = alp0[0];
    uint4 pa1h = ahp1[0], pa1l = alp1[0];
    float4 pw0 = *(const float4*)(wptr);
    float4 pw1 = *(const float4*)(wptr + 4);

    for (int ch = 0; ch < NCH2; ch++) {
        // stage from prefetched registers
        *(uint4*)(sAH + aoff0) = pa0h;
        *(uint4*)(sAL + aoff0) = pa0l;
        *(uint4*)(sAH + aoff1) = pa1h;
        *(uint4*)(sAL + aoff1) = pa1l;
        split8(pw0, pw1, sWH + woff, sWL + woff);
        __syncthreads();

        // prefetch next chunk (hidden behind MMAs)
        if (ch + 1 < NCH2) {
            int kq = (ch + 1) * (KC / 8);
            int kn = (ch + 1) * KC;
            pa0h = ahp0[kq]; pa0l = alp0[kq];
            pa1h = ahp1[kq]; pa1l = alp1[kq];
            pw0 = *(const float4*)(wptr + kn);
            pw1 = *(const float4*)(wptr + kn + 4);
        }

#pragma unroll
        for (int ks = 0; ks < 2; ks++) {
            int kb = ks * 16;
            uint32_t bwh[4], bwl[4];
            ldsm4(bwh, lds_addr(bWH, nw, kb, lane));
            ldsm4(bwl, lds_addr(bWL, nw, kb, lane));
#pragma unroll
            for (int mf = 0; mf < 4; mf++) {
                uint32_t ah[4], al[4];
                ldsm4(ah, lds_addr(bAH, mw + mf * 16, kb, lane));
                ldsm4(al, lds_addr(bAL, mw + mf * 16, kb, lane));
#pragma unroll
                for (int nf = 0; nf < 2; nf++) {
                    mma16816(acc[mf][nf], ah, bwh[nf], bwh[nf + 2]);
                    mma16816(acc[mf][nf], ah, bwl[nf], bwl[nf + 2]);
                    mma16816(acc[mf][nf], al, bwh[nf], bwh[nf + 2]);
                }
            }
        }
        __syncthreads();
    }

    // epilogue: scale by routing weight, scatter to per-slot y
#pragma unroll
    for (int mf = 0; mf < 4; mf++) {
#pragma unroll
        for (int nf = 0; nf < 2; nf++) {
            int ml = mw + mf * 16 + (lane >> 2);
            int ng = hb + nw + nf * 8 + ((lane & 3) << 1);
#pragma unroll
            for (int h = 0; h < 2; h++) {
                int m = ml + h * 8;
                int p = slots[m];
                if (p >= 0) {
                    float w = swt[m];
                    float2 o;
                    o.x = acc[mf][nf][h * 2] * w;
                    o.y = acc[mf][nf][h * 2 + 1] * w;
                    *(float2*)(g_y + (size_t)p * HDIM + ng) = o;
                }
            }
        }
    }
}

// ---------------- combine ----------------
__global__ void combine_kernel(float* __restrict__ out) {
    const int HQ = HDIM / 4;
    int i = blockIdx.x * blockDim.x + threadIdx.x;
    if (i >= NTOK * HQ) return;
    int t = i / HQ, hq = i - t * HQ;
    const float4* y4 = (const float4*)g_y;
    float4 a = y4[(size_t)(2 * t) * HQ + hq];
    float4 b = y4[(size_t)(2 * t + 1) * HQ + hq];
    float4 o;
    o.x = a.x + b.x; o.y = a.y + b.y; o.z = a.z + b.z; o.w = a.w + b.w;
    ((float4*)out)[(size_t)t * HQ + hq] = o;
}

extern "C" void kernel_launch(void* const* d_in, const int* in_sizes, int n_in,
                              void* d_out, int out_size) {
    const float* x    = (const float*)d_in[0];
    const int*   ei   = (const int*)d_in[1];
    const float* ew   = (const float*)d_in[2];
    const float* gate = (const float*)d_in[3];
    const float* up   = (const float*)d_in[4];
    const float* down = (const float*)d_in[5];
    float* out = (float*)d_out;

    route_kernel<<<1, 256>>>(ei);
    gemm1_mma<<<dim3(IDIM / TN, TILE_MAX), 256>>>(x, gate, up);
    gemm2_mma<<<dim3(HDIM / TN, TILE_MAX), 256>>>(down, ew);
    combine_kernel<<<(NTOK * (HDIM / 4) + 255) / 256, 256>>>(out);
}

// round 11
// speedup vs baseline: 1.6475x; 1.0022x over previous
#include <cuda_runtime.h>
#include <cuda_bf16.h>
#include <math.h>
#include <stdint.h>

// ---------------- problem constants ----------------
#define HDIM 1024
#define IDIM 4096
#define NEXP 8
#define NTOK 4096          // B*S
#define NSLOT 8192         // NTOK*TOPK
#define TM 128             // CTA M tile
#define TN 64              // CTA N tile
#define KC 32              // K elems per chunk
#define NCH1 (HDIM / KC)   // 32
#define NCH2 (IDIM / KC)   // 128
#define PAD_MAX 9216
#define TILE_MAX 72
#define STRD 40            // smem row stride in elems (32 + 8 pad) -> 80B rows

// ---------------- device scratch (static, no allocs) ----------------
__device__ int   g_perm[PAD_MAX];
__device__ int   g_tile_expert[TILE_MAX];
__device__ int   g_tile_row0[TILE_MAX];
// act stored pre-split as bf16 hi/lo, row-major [PAD_MAX][IDIM]
__device__ uint4 g_act_hi[(size_t)PAD_MAX * IDIM / 8];
__device__ uint4 g_act_lo[(size_t)PAD_MAX * IDIM / 8];
__device__ float g_y[(size_t)NSLOT * HDIM];

// ---------------- helpers ----------------
__device__ __forceinline__ uint32_t smem_to_u32(const void* p) {
    uint32_t a;
    asm("{ .reg .u64 t; cvta.to.shared.u64 t, %1; cvt.u32.u64 %0, t; }" : "=r"(a) : "l"(p));
    return a;
}
__device__ __forceinline__ void ldsm4(uint32_t* r, uint32_t addr) {
    asm volatile("ldmatrix.sync.aligned.m8n8.x4.shared.b16 {%0,%1,%2,%3}, [%4];"
                 : "=r"(r[0]), "=r"(r[1]), "=r"(r[2]), "=r"(r[3]) : "r"(addr));
}
__device__ __forceinline__ void mma16816(float* c, const uint32_t* a, uint32_t b0, uint32_t b1) {
    asm volatile(
        "mma.sync.aligned.m16n8k16.row.col.f32.bf16.bf16.f32 "
        "{%0,%1,%2,%3}, {%4,%5,%6,%7}, {%8,%9}, {%0,%1,%2,%3};"
        : "+f"(c[0]), "+f"(c[1]), "+f"(c[2]), "+f"(c[3])
        : "r"(a[0]), "r"(a[1]), "r"(a[2]), "r"(a[3]), "r"(b0), "r"(b1));
}
// ldmatrix x4 address for a 16x16 block at (row, k) in a [.][STRD] bf16 tile
__device__ __forceinline__ uint32_t lds_addr(uint32_t base, int row, int k, int lane) {
    int r = row + (lane & 15);
    int kk = k + ((lane >> 4) << 3);
    return base + (uint32_t)(r * (STRD * 2) + kk * 2);
}
__device__ __forceinline__ float silu_mul(float g, float u) {
    return g * u / (1.0f + expf(-g));
}
__device__ __forceinline__ void split8(float4 v0, float4 v1, void* ph, void* pl) {
    float f[8] = {v0.x, v0.y, v0.z, v0.w, v1.x, v1.y, v1.z, v1.w};
    union { __nv_bfloat16 b[8]; uint4 u; } H, L;
#pragma unroll
    for (int j = 0; j < 8; j++) {
        __nv_bfloat16 h = __float2bfloat16(f[j]);
        H.b[j] = h;
        L.b[j] = __float2bfloat16(f[j] - __bfloat162float(h));
    }
    *(uint4*)ph = H.u;
    *(uint4*)pl = L.u;
}

// ---------------- routing (output-order invariant) ----------------
__global__ void route_kernel(const int* __restrict__ ei) {
    __shared__ int cnt[NEXP];
    __shared__ int cur[NEXP];
    int tid = threadIdx.x;
    if (tid < NEXP) cnt[tid] = 0;
    __syncthreads();
    for (int s = tid; s < NSLOT; s += blockDim.x) atomicAdd(&cnt[ei[s]], 1);
    __syncthreads();
    if (tid == 0) {
        int base = 0, tile = 0;
        for (int e = 0; e < NEXP; e++) {
            cur[e] = base;
            int nt = (cnt[e] + TM - 1) / TM;
            for (int j = 0; j < nt; j++) { g_tile_expert[tile] = e; g_tile_row0[tile] = base + j * TM; tile++; }
            base += nt * TM;
        }
        for (; tile < TILE_MAX; tile++) g_tile_expert[tile] = -1;
    }
    __syncthreads();
    for (int r = tid; r < PAD_MAX; r += blockDim.x) g_perm[r] = -1;
    __syncthreads();
    for (int s = tid; s < NSLOT; s += blockDim.x) {
        int e = ei[s];
        int pos = atomicAdd(&cur[e], 1);
        g_perm[pos] = s;
    }
}

// ---------------- GEMM1: act = silu(x.gateT) * (x.upT) ----------------
// Weight tiles are prefetched one chunk ahead into registers (LDG hidden
// behind the MMA section); x stays loop-top (mostly L2 hits, rows shared
// across all 64 i-tile CTAs).
__global__ __launch_bounds__(256, 2)
void gemm1_mma(const float* __restrict__ x,
               const float* __restrict__ gate,
               const float* __restrict__ up) {
    int e = g_tile_expert[blockIdx.y];
    if (e < 0) return;
    int row0 = g_tile_row0[blockIdx.y];
    int i0 = blockIdx.x * TN;

    __shared__ __align__(16) __nv_bfloat16 sXH[TM * STRD], sXL[TM * STRD];
    __shared__ __align__(16) __nv_bfloat16 sGH[TN * STRD], sGL[TN * STRD];
    __shared__ __align__(16) __nv_bfloat16 sUH[TN * STRD], sUL[TN * STRD];
    __shared__ int toks[TM];

    int tid = threadIdx.x;
    int lane = tid & 31, wid = tid >> 5;
    int mw = (wid >> 2) * 64;      // warp M offset (0 or 64)
    int nw = (wid & 3) * 16;       // warp N offset

    if (tid < TM) {
        int p = g_perm[row0 + tid];
        toks[tid] = (p >= 0) ? (p >> 1) : -1;
    }
    __syncthreads();

    uint32_t bXH = smem_to_u32(sXH), bXL = smem_to_u32(sXL);
    uint32_t bGH = smem_to_u32(sGH), bGL = smem_to_u32(sGL);
    uint32_t bUH = smem_to_u32(sUH), bUL = smem_to_u32(sUL);

    // weight-staging task for this thread (fixed across chunks)
    int wr = tid >> 2, wk0 = (tid & 3) << 3;
    const float* gptr = gate + ((size_t)e * IDIM + i0 + wr) * HDIM + wk0;
    const float* uptr = up   + ((size_t)e * IDIM + i0 + wr) * HDIM + wk0;
    int woff = wr * STRD + wk0;

    float cg[4][2][4], cu[4][2][4];
#pragma unroll
    for (int mf = 0; mf < 4; mf++)
#pragma unroll
        for (int nf = 0; nf < 2; nf++)
#pragma unroll
            for (int q = 0; q < 4; q++) { cg[mf][nf][q] = 0.f; cu[mf][nf][q] = 0.f; }

    // prologue: prefetch weights for chunk 0
    float4 pg0 = *(const float4*)(gptr);
    float4 pg1 = *(const float4*)(gptr + 4);
    float4 pu0 = *(const float4*)(uptr);
    float4 pu1 = *(const float4*)(uptr + 4);

    for (int ch = 0; ch < NCH1; ch++) {
        int h0 = ch * KC;
        // stage x (gathered rows): 512 tasks of 8 elems
#pragma unroll
        for (int l = 0; l < 2; l++) {
            int s = tid + l * 256;
            int row = s >> 2, k0 = (s & 3) << 3;
            int tok = toks[row];
            float4 v0 = make_float4(0.f, 0.f, 0.f, 0.f), v1 = v0;
            if (tok >= 0) {
                const float4* p = (const float4*)(x + (size_t)tok * HDIM + h0 + k0);
                v0 = p[0]; v1 = p[1];
            }
            int off = row * STRD + k0;
            split8(v0, v1, sXH + off, sXL + off);
        }
        // stage weights from prefetched registers
        split8(pg0, pg1, sGH + woff, sGL + woff);
        split8(pu0, pu1, sUH + woff, sUL + woff);
        __syncthreads();

        // prefetch next chunk's weights (latency hidden behind MMAs below)
        if (ch + 1 < NCH1) {
            int hn = (ch + 1) * KC;
            pg0 = *(const float4*)(gptr + hn);
            pg1 = *(const float4*)(gptr + hn + 4);
            pu0 = *(const float4*)(uptr + hn);
            pu1 = *(const float4*)(uptr + hn + 4);
        }

#pragma unroll
        for (int ks = 0; ks < 2; ks++) {
            int kb = ks * 16;
            uint32_t bgh[4], bgl[4], buh[4], bul[4];
            ldsm4(bgh, lds_addr(bGH, nw, kb, lane));
            ldsm4(bgl, lds_addr(bGL, nw, kb, lane));
            ldsm4(buh, lds_addr(bUH, nw, kb, lane));
            ldsm4(bul, lds_addr(bUL, nw, kb, lane));
#pragma unroll
            for (int mf = 0; mf < 4; mf++) {
                uint32_t ah[4], al[4];
                ldsm4(ah, lds_addr(bXH, mw + mf * 16, kb, lane));
                ldsm4(al, lds_addr(bXL, mw + mf * 16, kb, lane));
#pragma unroll
                for (int nf = 0; nf < 2; nf++) {
                    mma16816(cg[mf][nf], ah, bgh[nf], bgh[nf + 2]);
                    mma16816(cg[mf][nf], ah, bgl[nf], bgl[nf + 2]);
                    mma16816(cg[mf][nf], al, bgh[nf], bgh[nf + 2]);
                    mma16816(cu[mf][nf], ah, buh[nf], buh[nf + 2]);
                    mma16816(cu[mf][nf], ah, bul[nf], bul[nf + 2]);
                    mma16816(cu[mf][nf], al, buh[nf], buh[nf + 2]);
                }
            }
        }
        __syncthreads();
    }

    // epilogue: silu*mul, split, store hi/lo bf16 act
    __nv_bfloat16* AH = (__nv_bfloat16*)g_act_hi;
    __nv_bfloat16* AL = (__nv_bfloat16*)g_act_lo;
#pragma unroll
    for (int mf = 0; mf < 4; mf++) {
#pragma unroll
        for (int nf = 0; nf < 2; nf++) {
            int mg = row0 + mw + mf * 16 + (lane >> 2);
            int ng = i0 + nw + nf * 8 + ((lane & 3) << 1);
#pragma unroll
            for (int h = 0; h < 2; h++) {
                float a0 = silu_mul(cg[mf][nf][h * 2],     cu[mf][nf][h * 2]);
                float a1 = silu_mul(cg[mf][nf][h * 2 + 1], cu[mf][nf][h * 2 + 1]);
                __nv_bfloat16 h0 = __float2bfloat16(a0), h1 = __float2bfloat16(a1);
                __nv_bfloat16 l0 = __float2bfloat16(a0 - __bfloat162float(h0));
                __nv_bfloat16 l1 = __float2bfloat16(a1 - __bfloat162float(h1));
                size_t idx = (size_t)(mg + h * 8) * IDIM + ng;
                *(__nv_bfloat162*)(AH + idx) = __halves2bfloat162(h0, h1);
                *(__nv_bfloat162*)(AL + idx) = __halves2bfloat162(l0, l1);
            }
        }
    }
}

// ---------------- GEMM2: y = ew * (act . downT) ----------------
// Both operands register-prefetched one chunk ahead (acc only 32 regs here).
__global__ __launch_bounds__(256, 2)
void gemm2_mma(const float* __restrict__ down,
               const float* __restrict__ ew) {
    int e = g_tile_expert[blockIdx.y];
    if (e < 0) return;
    int row0 = g_tile_row0[blockIdx.y];
    int hb = blockIdx.x * TN;

    __shared__ __align__(16) __nv_bfloat16 sAH[TM * STRD], sAL[TM * STRD];
    __shared__ __align__(16) __nv_bfloat16 sWH[TN * STRD], sWL[TN * STRD];
    __shared__ int   slots[TM];
    __shared__ float swt[TM];

    int tid = threadIdx.x;
    int lane = tid & 31, wid = tid >> 5;
    int mw = (wid >> 2) * 64;
    int nw = (wid & 3) * 16;

    if (tid < TM) {
        int p = g_perm[row0 + tid];
        slots[tid] = p;
        swt[tid] = (p >= 0) ? ew[p] : 0.f;
    }
    __syncthreads();

    uint32_t bAH = smem_to_u32(sAH), bAL = smem_to_u32(sAL);
    uint32_t bWH = smem_to_u32(sWH), bWL = smem_to_u32(sWL);

    // fixed per-thread staging tasks
    // act: 2 tasks (rows tid>>2 and (tid+256)>>2)
    int ar0 = tid >> 2, ak0 = tid & 3;
    int ar1 = (tid + 256) >> 2, ak1 = ak0;
    const uint4* ahp0 = g_act_hi + (size_t)(row0 + ar0) * (IDIM / 8) + ak0;
    const uint4* alp0 = g_act_lo + (size_t)(row0 + ar0) * (IDIM / 8) + ak0;
    const uint4* ahp1 = g_act_hi + (size_t)(row0 + ar1) * (IDIM / 8) + ak1;
    const uint4* alp1 = g_act_lo + (size_t)(row0 + ar1) * (IDIM / 8) + ak1;
    int aoff0 = ar0 * STRD + (ak0 << 3);
    int aoff1 = ar1 * STRD + (ak1 << 3);
    // down: 1 task
    int wr = tid >> 2, wk0 = (tid & 3) << 3;
    const float* wptr = down + ((size_t)e * HDIM + hb + wr) * IDIM + wk0;
    int woff = wr * STRD + wk0;

    float acc[4][2][4];
#pragma unroll
    for (int mf = 0; mf < 4; mf++)
#pragma unroll
        for (int nf = 0; nf < 2; nf++)
#pragma unroll
            for (int q = 0; q < 4; q++) acc[mf][nf][q] = 0.f;

    // prologue: prefetch chunk 0
    uint4 pa0h = ahp0[0], pa0l = alp0[0];
    uint4 pa1h = ahp1[0], pa1l = alp1[0];
    float4 pw0 = *(const float4*)(wptr);
    float4 pw1 = *(const float4*)(wptr + 4);

    for (int ch = 0; ch < NCH2; ch++) {
        // stage from prefetched registers
        *(uint4*)(sAH + aoff0) = pa0h;
        *(uint4*)(sAL + aoff0) = pa0l;
        *(uint4*)(sAH + aoff1) = pa1h;
        *(uint4*)(sAL + aoff1) = pa1l;
        split8(pw0, pw1, sWH + woff, sWL + woff);
        __syncthreads();

        // prefetch next chunk (hidden behind MMAs)
        if (ch + 1 < NCH2) {
            int kq = (ch + 1) * (KC / 8);
            int kn = (ch + 1) * KC;
            pa0h = ahp0[kq]; pa0l = alp0[kq];
            pa1h = ahp1[kq]; pa1l = alp1[kq];
            pw0 = *(const float4*)(wptr + kn);
            pw1 = *(const float4*)(wptr + kn + 4);
        }

#pragma unroll
        for (int ks = 0; ks < 2; ks++) {
            int kb = ks * 16;
            uint32_t bwh[4], bwl[4];
            ldsm4(bwh, lds_addr(bWH, nw, kb, lane));
            ldsm4(bwl, lds_addr(bWL, nw, kb, lane));
#pragma unroll
            for (int mf = 0; mf < 4; mf++) {
                uint32_t ah[4], al[4];
                ldsm4(ah, lds_addr(bAH, mw + mf * 16, kb, lane));
                ldsm4(al, lds_addr(bAL, mw + mf * 16, kb, lane));
#pragma unroll
                for (int nf = 0; nf < 2; nf++) {
                    mma16816(acc[mf][nf], ah, bwh[nf], bwh[nf + 2]);
                    mma16816(acc[mf][nf], ah, bwl[nf], bwl[nf + 2]);
                    mma16816(acc[mf][nf], al, bwh[nf], bwh[nf + 2]);
                }
            }
        }
        __syncthreads();
    }

    // epilogue: scale by routing weight, scatter to per-slot y
#pragma unroll
    for (int mf = 0; mf < 4; mf++) {
#pragma unroll
        for (int nf = 0; nf < 2; nf++) {
            int ml = mw + mf * 16 + (lane >> 2);
            int ng = hb + nw + nf * 8 + ((lane & 3) << 1);
#pragma unroll
            for (int h = 0; h < 2; h++) {
                int m = ml + h * 8;
                int p = slots[m];
                if (p >= 0) {
                    float w = swt[m];
                    float2 o;
                    o.x = acc[mf][nf][h * 2] * w;
                    o.y = acc[mf][nf][h * 2 + 1] * w;
                    *(float2*)(g_y + (size_t)p * HDIM + ng) = o;
                }
            }
        }
    }
}

// ---------------- combine ----------------
__global__ void combine_kernel(float* __restrict__ out) {
    const int HQ = HDIM / 4;
    int i = blockIdx.x * blockDim.x + threadIdx.x;
    if (i >= NTOK * HQ) return;
    int t = i / HQ, hq = i - t * HQ;
    const float4* y4 = (const float4*)g_y;
    float4 a = y4[(size_t)(2 * t) * HQ + hq];
    float4 b = y4[(size_t)(2 * t + 1) * HQ + hq];
    float4 o;
    o.x = a.x + b.x; o.y = a.y + b.y; o.z = a.z + b.z; o.w = a.w + b.w;
    ((float4*)out)[(size_t)t * HQ + hq] = o;
}

extern "C" void kernel_launch(void* const* d_in, const int* in_sizes, int n_in,
                              void* d_out, int out_size) {
    const float* x    = (const float*)d_in[0];
    const int*   ei   = (const int*)d_in[1];
    const float* ew   = (const float*)d_in[2];
    const float* gate = (const float*)d_in[3];
    const float* up   = (const float*)d_in[4];
    const float* down = (const float*)d_in[5];
    float* out = (float*)d_out;

    route_kernel<<<1, 256>>>(ei);
    gemm1_mma<<<dim3(IDIM / TN, TILE_MAX), 256>>>(x, gate, up);
    gemm2_mma<<<dim3(HDIM / TN, TILE_MAX), 256>>>(down, ew);
    combine_kernel<<<(NTOK * (HDIM / 4) + 255) / 256, 256>>>(out);
}